// round 1
// baseline (speedup 1.0000x reference)
#include <cuda_runtime.h>
#include <cuda_bf16.h>
#include <math.h>

// ---------------------------------------------------------------------------
// AutoformerDecoderLayer: B=8, L=1024, D=512, H=8, dk=64, DFF=2048
// Round 0: exact fp32 SIMT baseline.
// ---------------------------------------------------------------------------

#define BB 8
#define LL 1024
#define DD 512
#define HH 8
#define DKH 64
#define DFF 2048
#define MM (BB*LL)          // 8192

// --------------------------- scratch (no allocs) ---------------------------
__device__ float g_q  [MM*DD];
__device__ float g_k  [MM*DD];
__device__ float g_v  [MM*DD];
__device__ float g_at [MM*DD];
__device__ float g_t  [MM*DD];
__device__ float g_m  [MM*DD];
__device__ float g_x  [MM*DD];
__device__ float g_ff [MM*DFF];

// ---------------------------------------------------------------------------
// GEMM: C[M,N] = A[M,K] @ W[N,K]^T + bias[N]  (+GELU) (+residual R)
// 128x128 block, BK=16, 256 threads, 8x8 microtile.
// ---------------------------------------------------------------------------
template<bool RES, bool GELU>
__global__ void __launch_bounds__(256)
gemm_bias_kernel(const float* __restrict__ A, const float* __restrict__ W,
                 const float* __restrict__ bias, const float* __restrict__ R,
                 float* __restrict__ C, int Mt, int Nt, int Kt)
{
    __shared__ float As[16][132];
    __shared__ float Bs[16][132];

    const int tid = threadIdx.x;
    const int m0 = blockIdx.y * 128;
    const int n0 = blockIdx.x * 128;
    const int tx = tid & 15;
    const int ty = tid >> 4;
    const int rowB = ty * 8;
    const int colB = tx * 8;

    float acc[8][8];
#pragma unroll
    for (int i = 0; i < 8; ++i)
#pragma unroll
        for (int j = 0; j < 8; ++j) acc[i][j] = 0.f;

    for (int k0 = 0; k0 < Kt; k0 += 16) {
#pragma unroll
        for (int it = 0; it < 2; ++it) {
            int f  = tid + (it << 8);        // 0..511
            int m  = f >> 2;                 // 0..127
            int k4 = (f & 3) << 2;           // 0,4,8,12
            float4 va = *(const float4*)&A[(size_t)(m0 + m) * Kt + k0 + k4];
            As[k4 + 0][m] = va.x; As[k4 + 1][m] = va.y;
            As[k4 + 2][m] = va.z; As[k4 + 3][m] = va.w;
            float4 vb = *(const float4*)&W[(size_t)(n0 + m) * Kt + k0 + k4];
            Bs[k4 + 0][m] = vb.x; Bs[k4 + 1][m] = vb.y;
            Bs[k4 + 2][m] = vb.z; Bs[k4 + 3][m] = vb.w;
        }
        __syncthreads();
#pragma unroll
        for (int kk = 0; kk < 16; ++kk) {
            float4 a0 = *(const float4*)&As[kk][rowB];
            float4 a1 = *(const float4*)&As[kk][rowB + 4];
            float4 b0 = *(const float4*)&Bs[kk][colB];
            float4 b1 = *(const float4*)&Bs[kk][colB + 4];
            float a[8] = {a0.x,a0.y,a0.z,a0.w,a1.x,a1.y,a1.z,a1.w};
            float b[8] = {b0.x,b0.y,b0.z,b0.w,b1.x,b1.y,b1.z,b1.w};
#pragma unroll
            for (int i = 0; i < 8; ++i)
#pragma unroll
                for (int j = 0; j < 8; ++j) acc[i][j] += a[i] * b[j];
        }
        __syncthreads();
    }

#pragma unroll
    for (int i = 0; i < 8; ++i) {
        size_t rowOff = (size_t)(m0 + rowB + i) * Nt + n0 + colB;
#pragma unroll
        for (int j = 0; j < 8; ++j) {
            float c = acc[i][j] + bias[n0 + colB + j];
            if (GELU) c = 0.5f * c * (1.f + erff(c * 0.70710678118654752f));
            if (RES)  c += R[rowOff + j];
            C[rowOff + j] = c;
        }
    }
}

// ---------------------------------------------------------------------------
// Flash attention, 64q x 64k tiles, dk=64. ALiBi-style bias -0.1*|q-k|,
// scale 1/8. Q^T, K^T/P^T (shared buffer), V in swizzled 16KB smem each.
// ---------------------------------------------------------------------------
__device__ __forceinline__ int swz(int srow, int col) {
    return srow * 64 + ((((col >> 2) ^ (srow & 15)) << 2) | (col & 3));
}
__device__ __forceinline__ float4 ld4s(const float* s, int srow, int col4) {
    return *(const float4*)&s[srow * 64 + (((col4 >> 2) ^ (srow & 15)) << 2)];
}

__global__ void __launch_bounds__(256)
attn_kernel(const float* __restrict__ Q, const float* __restrict__ K,
            const float* __restrict__ V, float* __restrict__ O)
{
    __shared__ float QsT[4096];   // [kk][r]  (swizzled)
    __shared__ float KP [4096];   // K^T, then P^T
    __shared__ float Vs [4096];   // [key][oc] (swizzled)

    const int tid = threadIdx.x;
    const int b = blockIdx.y >> 3;
    const int h = blockIdx.y & 7;
    const int l0 = blockIdx.x << 6;
    const size_t hb = ((size_t)b * LL) * DD + h * DKH;

#pragma unroll
    for (int i = 0; i < 4; ++i) {
        int f  = tid + (i << 8);
        int r  = f >> 4;
        int k4 = (f & 15) << 2;
        float4 v = *(const float4*)&Q[hb + (size_t)(l0 + r) * DD + k4];
        QsT[swz(k4    , r)] = v.x;
        QsT[swz(k4 + 1, r)] = v.y;
        QsT[swz(k4 + 2, r)] = v.z;
        QsT[swz(k4 + 3, r)] = v.w;
    }

    const int c0 = (tid & 15) << 2;   // key / out-col group
    const int r0 = (tid >> 4) << 2;   // query-row group (16 consecutive tids share rows)

    float o[16];
#pragma unroll
    for (int t = 0; t < 16; ++t) o[t] = 0.f;
    float mrow[4] = {-1e30f, -1e30f, -1e30f, -1e30f};
    float lrow[4] = {0.f, 0.f, 0.f, 0.f};

#pragma unroll 1
    for (int kt = 0; kt < 16; ++kt) {
        const int kbase = kt << 6;
        __syncthreads();                      // prev PV done before KP overwrite
#pragma unroll
        for (int i = 0; i < 4; ++i) {
            int f  = tid + (i << 8);
            int r  = f >> 4;
            int k4 = (f & 15) << 2;
            float4 v = *(const float4*)&K[hb + (size_t)(kbase + r) * DD + k4];
            KP[swz(k4    , r)] = v.x;
            KP[swz(k4 + 1, r)] = v.y;
            KP[swz(k4 + 2, r)] = v.z;
            KP[swz(k4 + 3, r)] = v.w;
            float4 w = *(const float4*)&V[hb + (size_t)(kbase + r) * DD + k4];
            *(float4*)&Vs[r * 64 + (((k4 >> 2) ^ (r & 15)) << 2)] = w;
        }
        __syncthreads();

        // S = Q K^T  (4x4 microtile)
        float s[16];
#pragma unroll
        for (int t = 0; t < 16; ++t) s[t] = 0.f;
#pragma unroll 8
        for (int kk = 0; kk < 64; ++kk) {
            float4 a  = ld4s(QsT, kk, r0);
            float4 bb = ld4s(KP , kk, c0);
            s[ 0] += a.x*bb.x; s[ 1] += a.x*bb.y; s[ 2] += a.x*bb.z; s[ 3] += a.x*bb.w;
            s[ 4] += a.y*bb.x; s[ 5] += a.y*bb.y; s[ 6] += a.y*bb.z; s[ 7] += a.y*bb.w;
            s[ 8] += a.z*bb.x; s[ 9] += a.z*bb.y; s[10] += a.z*bb.z; s[11] += a.z*bb.w;
            s[12] += a.w*bb.x; s[13] += a.w*bb.y; s[14] += a.w*bb.z; s[15] += a.w*bb.w;
        }

        // online softmax (rows owned by 16 consecutive lanes -> xor shfl 1..8)
#pragma unroll
        for (int i = 0; i < 4; ++i) {
            const int qpos = l0 + r0 + i;
            float sm[4];
#pragma unroll
            for (int j = 0; j < 4; ++j) {
                int kpos = kbase + c0 + j;
                sm[j] = s[i*4 + j] * 0.125f - 0.1f * fabsf((float)(qpos - kpos));
            }
            float rm = fmaxf(fmaxf(sm[0], sm[1]), fmaxf(sm[2], sm[3]));
#pragma unroll
            for (int off = 1; off < 16; off <<= 1)
                rm = fmaxf(rm, __shfl_xor_sync(0xffffffffu, rm, off));
            float mn = fmaxf(mrow[i], rm);
            float alpha = __expf(mrow[i] - mn);
            mrow[i] = mn;
            float rs = 0.f;
#pragma unroll
            for (int j = 0; j < 4; ++j) { sm[j] = __expf(sm[j] - mn); rs += sm[j]; }
#pragma unroll
            for (int off = 1; off < 16; off <<= 1)
                rs += __shfl_xor_sync(0xffffffffu, rs, off);
            lrow[i] = lrow[i] * alpha + rs;
#pragma unroll
            for (int j = 0; j < 4; ++j) { o[i*4 + j] *= alpha; s[i*4 + j] = sm[j]; }
        }

        __syncthreads();                      // S reads of KP done
        // store P^T into KP: PsT[key][row]
#pragma unroll
        for (int j = 0; j < 4; ++j) {
            float4 pv = make_float4(s[j], s[4 + j], s[8 + j], s[12 + j]);
            *(float4*)&KP[(c0 + j) * 64 + (((r0 >> 2) ^ ((c0 + j) & 15)) << 2)] = pv;
        }
        __syncthreads();

        // O += P^T-gather * V
#pragma unroll 8
        for (int kk = 0; kk < 64; ++kk) {
            float4 a  = ld4s(KP, kk, r0);     // P[r0..r0+3][kk]
            float4 bb = ld4s(Vs, kk, c0);     // V[kk][c0..c0+3]
            o[ 0] += a.x*bb.x; o[ 1] += a.x*bb.y; o[ 2] += a.x*bb.z; o[ 3] += a.x*bb.w;
            o[ 4] += a.y*bb.x; o[ 5] += a.y*bb.y; o[ 6] += a.y*bb.z; o[ 7] += a.y*bb.w;
            o[ 8] += a.z*bb.x; o[ 9] += a.z*bb.y; o[10] += a.z*bb.z; o[11] += a.z*bb.w;
            o[12] += a.w*bb.x; o[13] += a.w*bb.y; o[14] += a.w*bb.z; o[15] += a.w*bb.w;
        }
    }

#pragma unroll
    for (int i = 0; i < 4; ++i) {
        float inv = 1.f / lrow[i];
        float4 w = make_float4(o[i*4]*inv, o[i*4+1]*inv, o[i*4+2]*inv, o[i*4+3]*inv);
        *(float4*)&O[hb + (size_t)(l0 + r0 + i) * DD + c0] = w;
    }
}

// ---------------------------------------------------------------------------
// Moving average: AvgPool1d(k=25, stride=1, pad=12, count_include_pad)
// sliding-window scan per (b,d) column over chunks of 32 rows.
// ---------------------------------------------------------------------------
__global__ void movavg_kernel(const float* __restrict__ in, float* __restrict__ out)
{
    const int d  = threadIdx.x;              // 0..511
    const int b  = blockIdx.y;
    const int l0 = blockIdx.x * 32;
    const float* p = in  + ((size_t)b * LL) * DD + d;
    float*       q = out + ((size_t)b * LL) * DD + d;

    float s = 0.f;
#pragma unroll 1
    for (int t = l0 - 12; t <= l0 + 12; ++t)
        if (t >= 0 && t < LL) s += p[(size_t)t * DD];
#pragma unroll 1
    for (int i = 0; i < 32; ++i) {
        const int l = l0 + i;
        q[(size_t)l * DD] = s * 0.04f;
        const int th = l + 13, tl = l - 12;
        if (th < LL)  s += p[(size_t)th * DD];
        if (tl >= 0)  s -= p[(size_t)tl * DD];
    }
}

// ---------------------------------------------------------------------------
// LayerNorm over D=512, one block per row.
// ---------------------------------------------------------------------------
__global__ void __launch_bounds__(128)
ln_kernel(const float* __restrict__ in, const float* __restrict__ g,
          const float* __restrict__ bb, float* __restrict__ out)
{
    const int row = blockIdx.x;
    const int tid = threadIdx.x;             // 128, 4 elems each
    const float4 v = ((const float4*)(in + (size_t)row * DD))[tid];
    float s  = v.x + v.y + v.z + v.w;
    float ss = v.x*v.x + v.y*v.y + v.z*v.z + v.w*v.w;
#pragma unroll
    for (int off = 16; off; off >>= 1) {
        s  += __shfl_xor_sync(0xffffffffu, s , off);
        ss += __shfl_xor_sync(0xffffffffu, ss, off);
    }
    __shared__ float sh[8];
    if ((tid & 31) == 0) { sh[tid >> 5] = s; sh[4 + (tid >> 5)] = ss; }
    __syncthreads();
    s  = sh[0] + sh[1] + sh[2] + sh[3];
    ss = sh[4] + sh[5] + sh[6] + sh[7];
    const float mu  = s * (1.f / DD);
    const float var = ss * (1.f / DD) - mu * mu;
    const float inv = rsqrtf(var + 1e-5f);
    const float4 gg = ((const float4*)g )[tid];
    const float4 bv = ((const float4*)bb)[tid];
    float4 r;
    r.x = (v.x - mu) * inv * gg.x + bv.x;
    r.y = (v.y - mu) * inv * gg.y + bv.y;
    r.z = (v.z - mu) * inv * gg.z + bv.z;
    r.w = (v.w - mu) * inv * gg.w + bv.w;
    ((float4*)(out + (size_t)row * DD))[tid] = r;
}

// ---------------------------------------------------------------------------
extern "C" void kernel_launch(void* const* d_in, const int* in_sizes, int n_in,
                              void* d_out, int out_size)
{
    (void)in_sizes; (void)n_in; (void)out_size;
    const float* x     = (const float*)d_in[0];
    const float* enc   = (const float*)d_in[1];
    const float* saWq  = (const float*)d_in[2];
    const float* sabq  = (const float*)d_in[3];
    const float* saWk  = (const float*)d_in[4];
    const float* sabk  = (const float*)d_in[5];
    const float* saWv  = (const float*)d_in[6];
    const float* sabv  = (const float*)d_in[7];
    const float* saWo  = (const float*)d_in[8];
    const float* sabo  = (const float*)d_in[9];
    const float* caWq  = (const float*)d_in[10];
    const float* cabq  = (const float*)d_in[11];
    const float* caWk  = (const float*)d_in[12];
    const float* cabk  = (const float*)d_in[13];
    const float* caWv  = (const float*)d_in[14];
    const float* cabv  = (const float*)d_in[15];
    const float* caWo  = (const float*)d_in[16];
    const float* cabo  = (const float*)d_in[17];
    const float* ffW1  = (const float*)d_in[18];
    const float* ffb1  = (const float*)d_in[19];
    const float* ffW2  = (const float*)d_in[20];
    const float* ffb2  = (const float*)d_in[21];
    const float* n1g   = (const float*)d_in[22];
    const float* n1b   = (const float*)d_in[23];
    const float* n2g   = (const float*)d_in[24];
    const float* n2b   = (const float*)d_in[25];
    const float* n3g   = (const float*)d_in[26];
    const float* n3b   = (const float*)d_in[27];
    float* out = (float*)d_out;

    float *q, *k, *v, *at, *t, *mm, *xx, *ff;
    cudaGetSymbolAddress((void**)&q , g_q);
    cudaGetSymbolAddress((void**)&k , g_k);
    cudaGetSymbolAddress((void**)&v , g_v);
    cudaGetSymbolAddress((void**)&at, g_at);
    cudaGetSymbolAddress((void**)&t , g_t);
    cudaGetSymbolAddress((void**)&mm, g_m);
    cudaGetSymbolAddress((void**)&xx, g_x);
    cudaGetSymbolAddress((void**)&ff, g_ff);

    const dim3 blk(256);
    const dim3 gProj(DD / 128, MM / 128);    // (4, 64)
    const dim3 gF1(DFF / 128, MM / 128);     // (16, 64)
    const dim3 gAttn(LL / 64, BB * HH);      // (16, 64)
    const dim3 gMov(LL / 32, BB);            // (32, 8)

    // ---- self attention ----
    gemm_bias_kernel<false,false><<<gProj, blk>>>(x, saWq, sabq, nullptr, q, MM, DD, DD);
    gemm_bias_kernel<false,false><<<gProj, blk>>>(x, saWk, sabk, nullptr, k, MM, DD, DD);
    gemm_bias_kernel<false,false><<<gProj, blk>>>(x, saWv, sabv, nullptr, v, MM, DD, DD);
    attn_kernel<<<gAttn, blk>>>(q, k, v, at);
    gemm_bias_kernel<true ,false><<<gProj, blk>>>(at, saWo, sabo, x, t, MM, DD, DD);
    movavg_kernel<<<gMov, 512>>>(t, mm);
    ln_kernel<<<MM, 128>>>(mm, n1g, n1b, xx);

    // ---- cross attention ----
    gemm_bias_kernel<false,false><<<gProj, blk>>>(xx , caWq, cabq, nullptr, q, MM, DD, DD);
    gemm_bias_kernel<false,false><<<gProj, blk>>>(enc, caWk, cabk, nullptr, k, MM, DD, DD);
    gemm_bias_kernel<false,false><<<gProj, blk>>>(enc, caWv, cabv, nullptr, v, MM, DD, DD);
    attn_kernel<<<gAttn, blk>>>(q, k, v, at);
    gemm_bias_kernel<true ,false><<<gProj, blk>>>(at, caWo, cabo, xx, t, MM, DD, DD);
    movavg_kernel<<<gMov, 512>>>(t, mm);
    ln_kernel<<<MM, 128>>>(mm, n2g, n2b, xx);

    // ---- feed-forward ----
    gemm_bias_kernel<false,true ><<<gF1  , blk>>>(xx, ffW1, ffb1, nullptr, ff, MM, DFF, DD);
    gemm_bias_kernel<true ,false><<<gProj, blk>>>(ff, ffW2, ffb2, xx, t, MM, DD, DFF);
    movavg_kernel<<<gMov, 512>>>(t, mm);
    ln_kernel<<<MM, 128>>>(mm, n3g, n3b, out);
}

// round 7
// speedup vs baseline: 1.4132x; 1.4132x over previous
#include <cuda_runtime.h>
#include <cuda_bf16.h>
#include <math.h>
#include <stdint.h>

// ---------------------------------------------------------------------------
// AutoformerDecoderLayer: B=8, L=1024, D=512, H=8, dk=64, DFF=2048
// Round 7: resubmit R6 (mma.sync tf32 GEMMs, static <=48KB smem).
// R2 evidence shows "container failed twice" occurs pre-compile => infra.
// ---------------------------------------------------------------------------

#define BB 8
#define LL 1024
#define DD 512
#define HH 8
#define DKH 64
#define DFF 2048
#define MM (BB*LL)          // 8192

// --------------------------- scratch (no allocs) ---------------------------
__device__ float g_q  [MM*DD];
__device__ float g_k  [MM*DD];
__device__ float g_v  [MM*DD];
__device__ float g_at [MM*DD];
__device__ float g_t  [MM*DD];
__device__ float g_m  [MM*DD];
__device__ float g_x  [MM*DD];
__device__ float g_ff [MM*DFF];

__device__ __forceinline__ float to_tf32(float x){
    uint32_t y;
    asm("cvt.rna.tf32.f32 %0, %1;" : "=r"(y) : "f"(x));
    return __uint_as_float(y);
}

// ---------------------------------------------------------------------------
// tf32 mma.sync GEMM: C[M,N] = A[M,K] @ W[N,K]^T (+bias, +GELU, +residual)
// CTA 128x128, BK=16 double-buffered, 256 thr (8 warps, warp tile 64x32).
// Static smem: As[2][128][20] + Bs[2][128][20] = 40960 B (<48KB, no opt-in).
// ---------------------------------------------------------------------------
#define SMS 20                         // padded row stride (floats)

__device__ __forceinline__ void mma_tf32(float* d, const uint32_t* a, const uint32_t* b){
    asm volatile(
        "mma.sync.aligned.m16n8k8.row.col.f32.tf32.tf32.f32 "
        "{%0,%1,%2,%3}, {%4,%5,%6,%7}, {%8,%9}, {%0,%1,%2,%3};"
        : "+f"(d[0]), "+f"(d[1]), "+f"(d[2]), "+f"(d[3])
        : "r"(a[0]), "r"(a[1]), "r"(a[2]), "r"(a[3]), "r"(b[0]), "r"(b[1]));
}

template<bool RES, bool GELU>
__global__ void __launch_bounds__(256, 1)
gemm_mma(const float* __restrict__ A, const float* __restrict__ W,
         const float* __restrict__ bias, const float* __restrict__ R,
         float* __restrict__ C, int Nt, int Kt)
{
    __shared__ float As[2][128][SMS];
    __shared__ float Bs[2][128][SMS];

    const int tid  = threadIdx.x;
    const int lane = tid & 31;
    const int wid  = tid >> 5;
    const int m0 = blockIdx.y * 128;
    const int n0 = blockIdx.x * 128;
    const int wm = (wid & 1) * 64;     // warp M offset (2 warps on M)
    const int wn = (wid >> 1) * 32;    // warp N offset (4 warps on N)
    const int r  = lane >> 2;          // 0..7
    const int cq = lane & 3;           // 0..3

    float acc[4][4][4];
#pragma unroll
    for (int mt = 0; mt < 4; ++mt)
#pragma unroll
        for (int nt = 0; nt < 4; ++nt)
#pragma unroll
            for (int e = 0; e < 4; ++e) acc[mt][nt][e] = 0.f;

    // fill mapping: 128 rows x 16 cols = 512 float4 per operand, 2 per thread
    const int fr0 = tid >> 2;          // rows fr0, fr0+64
    const int fc4 = (tid & 3) << 2;    // 0,4,8,12

    // initial fill of stage 0
#pragma unroll
    for (int i = 0; i < 2; ++i) {
        const int row = fr0 + (i << 6);
        float4 va = *(const float4*)&A[(size_t)(m0 + row) * Kt + fc4];
        va.x = to_tf32(va.x); va.y = to_tf32(va.y);
        va.z = to_tf32(va.z); va.w = to_tf32(va.w);
        *(float4*)&As[0][row][fc4] = va;
        float4 vb = *(const float4*)&W[(size_t)(n0 + row) * Kt + fc4];
        vb.x = to_tf32(vb.x); vb.y = to_tf32(vb.y);
        vb.z = to_tf32(vb.z); vb.w = to_tf32(vb.w);
        *(float4*)&Bs[0][row][fc4] = vb;
    }
    __syncthreads();

    const int S = Kt >> 4;
#pragma unroll 1
    for (int s = 0; s < S; ++s) {
        const int cur = s & 1;

        // stage next chunk into registers
        float4 pa[2], pb[2];
        if (s + 1 < S) {
            const int k0 = (s + 1) << 4;
#pragma unroll
            for (int i = 0; i < 2; ++i) {
                const int row = fr0 + (i << 6);
                pa[i] = *(const float4*)&A[(size_t)(m0 + row) * Kt + k0 + fc4];
                pb[i] = *(const float4*)&W[(size_t)(n0 + row) * Kt + k0 + fc4];
            }
        }

        // compute on current buffer: 2 k-steps of 8
#pragma unroll
        for (int ks = 0; ks < 2; ++ks) {
            const int kc = ks << 3;
            uint32_t af[4][4], bf[4][2];
#pragma unroll
            for (int mt = 0; mt < 4; ++mt) {
                const int mr = wm + mt * 16 + r;
                af[mt][0] = __float_as_uint(As[cur][mr    ][kc + cq    ]);
                af[mt][1] = __float_as_uint(As[cur][mr + 8][kc + cq    ]);
                af[mt][2] = __float_as_uint(As[cur][mr    ][kc + cq + 4]);
                af[mt][3] = __float_as_uint(As[cur][mr + 8][kc + cq + 4]);
            }
#pragma unroll
            for (int nt = 0; nt < 4; ++nt) {
                const int nr = wn + nt * 8 + r;
                bf[nt][0] = __float_as_uint(Bs[cur][nr][kc + cq    ]);
                bf[nt][1] = __float_as_uint(Bs[cur][nr][kc + cq + 4]);
            }
#pragma unroll
            for (int mt = 0; mt < 4; ++mt)
#pragma unroll
                for (int nt = 0; nt < 4; ++nt)
                    mma_tf32(acc[mt][nt], af[mt], bf[nt]);
        }

        // store staged chunk into the other buffer
        if (s + 1 < S) {
            const int nxt = cur ^ 1;
#pragma unroll
            for (int i = 0; i < 2; ++i) {
                const int row = fr0 + (i << 6);
                float4 va = pa[i];
                va.x = to_tf32(va.x); va.y = to_tf32(va.y);
                va.z = to_tf32(va.z); va.w = to_tf32(va.w);
                *(float4*)&As[nxt][row][fc4] = va;
                float4 vb = pb[i];
                vb.x = to_tf32(vb.x); vb.y = to_tf32(vb.y);
                vb.z = to_tf32(vb.z); vb.w = to_tf32(vb.w);
                *(float4*)&Bs[nxt][row][fc4] = vb;
            }
            __syncthreads();
        }
    }

    // ---- epilogue ----
#pragma unroll
    for (int mt = 0; mt < 4; ++mt) {
#pragma unroll
        for (int half = 0; half < 2; ++half) {
            const int row = m0 + wm + mt * 16 + r + half * 8;
#pragma unroll
            for (int nt = 0; nt < 4; ++nt) {
                const int col = n0 + wn + nt * 8 + 2 * cq;
                float v0 = acc[mt][nt][half * 2 + 0];
                float v1 = acc[mt][nt][half * 2 + 1];
                float2 bv = *(const float2*)&bias[col];
                v0 += bv.x; v1 += bv.y;
                if (GELU) {
                    v0 = 0.5f * v0 * (1.f + erff(v0 * 0.70710678118654752f));
                    v1 = 0.5f * v1 * (1.f + erff(v1 * 0.70710678118654752f));
                }
                if (RES) {
                    float2 rv = *(const float2*)&R[(size_t)row * Nt + col];
                    v0 += rv.x; v1 += rv.y;
                }
                *(float2*)&C[(size_t)row * Nt + col] = make_float2(v0, v1);
            }
        }
    }
}

// ---------------------------------------------------------------------------
// Flash attention, 64q x 64k tiles, dk=64 (SIMT fp32, unchanged).
// ---------------------------------------------------------------------------
__device__ __forceinline__ int swz(int srow, int col) {
    return srow * 64 + ((((col >> 2) ^ (srow & 15)) << 2) | (col & 3));
}
__device__ __forceinline__ float4 ld4s(const float* s, int srow, int col4) {
    return *(const float4*)&s[srow * 64 + (((col4 >> 2) ^ (srow & 15)) << 2)];
}

__global__ void __launch_bounds__(256)
attn_kernel(const float* __restrict__ Q, const float* __restrict__ K,
            const float* __restrict__ V, float* __restrict__ O)
{
    __shared__ float QsT[4096];
    __shared__ float KP [4096];
    __shared__ float Vs [4096];

    const int tid = threadIdx.x;
    const int b = blockIdx.y >> 3;
    const int h = blockIdx.y & 7;
    const int l0 = blockIdx.x << 6;
    const size_t hb = ((size_t)b * LL) * DD + h * DKH;

#pragma unroll
    for (int i = 0; i < 4; ++i) {
        int f  = tid + (i << 8);
        int r  = f >> 4;
        int k4 = (f & 15) << 2;
        float4 v = *(const float4*)&Q[hb + (size_t)(l0 + r) * DD + k4];
        QsT[swz(k4    , r)] = v.x;
        QsT[swz(k4 + 1, r)] = v.y;
        QsT[swz(k4 + 2, r)] = v.z;
        QsT[swz(k4 + 3, r)] = v.w;
    }

    const int c0 = (tid & 15) << 2;
    const int r0 = (tid >> 4) << 2;

    float o[16];
#pragma unroll
    for (int t = 0; t < 16; ++t) o[t] = 0.f;
    float mrow[4] = {-1e30f, -1e30f, -1e30f, -1e30f};
    float lrow[4] = {0.f, 0.f, 0.f, 0.f};

#pragma unroll 1
    for (int kt = 0; kt < 16; ++kt) {
        const int kbase = kt << 6;
        __syncthreads();
#pragma unroll
        for (int i = 0; i < 4; ++i) {
            int f  = tid + (i << 8);
            int r  = f >> 4;
            int k4 = (f & 15) << 2;
            float4 v = *(const float4*)&K[hb + (size_t)(kbase + r) * DD + k4];
            KP[swz(k4    , r)] = v.x;
            KP[swz(k4 + 1, r)] = v.y;
            KP[swz(k4 + 2, r)] = v.z;
            KP[swz(k4 + 3, r)] = v.w;
            float4 w = *(const float4*)&V[hb + (size_t)(kbase + r) * DD + k4];
            *(float4*)&Vs[r * 64 + (((k4 >> 2) ^ (r & 15)) << 2)] = w;
        }
        __syncthreads();

        float s[16];
#pragma unroll
        for (int t = 0; t < 16; ++t) s[t] = 0.f;
#pragma unroll 8
        for (int kk = 0; kk < 64; ++kk) {
            float4 a  = ld4s(QsT, kk, r0);
            float4 bb = ld4s(KP , kk, c0);
            s[ 0] += a.x*bb.x; s[ 1] += a.x*bb.y; s[ 2] += a.x*bb.z; s[ 3] += a.x*bb.w;
            s[ 4] += a.y*bb.x; s[ 5] += a.y*bb.y; s[ 6] += a.y*bb.z; s[ 7] += a.y*bb.w;
            s[ 8] += a.z*bb.x; s[ 9] += a.z*bb.y; s[10] += a.z*bb.z; s[11] += a.z*bb.w;
            s[12] += a.w*bb.x; s[13] += a.w*bb.y; s[14] += a.w*bb.z; s[15] += a.w*bb.w;
        }

#pragma unroll
        for (int i = 0; i < 4; ++i) {
            const int qpos = l0 + r0 + i;
            float sm[4];
#pragma unroll
            for (int j = 0; j < 4; ++j) {
                int kpos = kbase + c0 + j;
                sm[j] = s[i*4 + j] * 0.125f - 0.1f * fabsf((float)(qpos - kpos));
            }
            float rm = fmaxf(fmaxf(sm[0], sm[1]), fmaxf(sm[2], sm[3]));
#pragma unroll
            for (int off = 1; off < 16; off <<= 1)
                rm = fmaxf(rm, __shfl_xor_sync(0xffffffffu, rm, off));
            float mn = fmaxf(mrow[i], rm);
            float alpha = __expf(mrow[i] - mn);
            mrow[i] = mn;
            float rs = 0.f;
#pragma unroll
            for (int j = 0; j < 4; ++j) { sm[j] = __expf(sm[j] - mn); rs += sm[j]; }
#pragma unroll
            for (int off = 1; off < 16; off <<= 1)
                rs += __shfl_xor_sync(0xffffffffu, rs, off);
            lrow[i] = lrow[i] * alpha + rs;
#pragma unroll
            for (int j = 0; j < 4; ++j) { o[i*4 + j] *= alpha; s[i*4 + j] = sm[j]; }
        }

        __syncthreads();
#pragma unroll
        for (int j = 0; j < 4; ++j) {
            float4 pv = make_float4(s[j], s[4 + j], s[8 + j], s[12 + j]);
            *(float4*)&KP[(c0 + j) * 64 + (((r0 >> 2) ^ ((c0 + j) & 15)) << 2)] = pv;
        }
        __syncthreads();

#pragma unroll 8
        for (int kk = 0; kk < 64; ++kk) {
            float4 a  = ld4s(KP, kk, r0);
            float4 bb = ld4s(Vs, kk, c0);
            o[ 0] += a.x*bb.x; o[ 1] += a.x*bb.y; o[ 2] += a.x*bb.z; o[ 3] += a.x*bb.w;
            o[ 4] += a.y*bb.x; o[ 5] += a.y*bb.y; o[ 6] += a.y*bb.z; o[ 7] += a.y*bb.w;
            o[ 8] += a.z*bb.x; o[ 9] += a.z*bb.y; o[10] += a.z*bb.z; o[11] += a.z*bb.w;
            o[12] += a.w*bb.x; o[13] += a.w*bb.y; o[14] += a.w*bb.z; o[15] += a.w*bb.w;
        }
    }

#pragma unroll
    for (int i = 0; i < 4; ++i) {
        float inv = 1.f / lrow[i];
        float4 w = make_float4(o[i*4]*inv, o[i*4+1]*inv, o[i*4+2]*inv, o[i*4+3]*inv);
        *(float4*)&O[hb + (size_t)(l0 + r0 + i) * DD + c0] = w;
    }
}

// ---------------------------------------------------------------------------
// Moving average (k=25, stride 1, pad 12, count_include_pad)
// ---------------------------------------------------------------------------
__global__ void movavg_kernel(const float* __restrict__ in, float* __restrict__ out)
{
    const int d  = threadIdx.x;
    const int b  = blockIdx.y;
    const int l0 = blockIdx.x * 32;
    const float* p = in  + ((size_t)b * LL) * DD + d;
    float*       q = out + ((size_t)b * LL) * DD + d;

    float s = 0.f;
#pragma unroll 1
    for (int t = l0 - 12; t <= l0 + 12; ++t)
        if (t >= 0 && t < LL) s += p[(size_t)t * DD];
#pragma unroll 1
    for (int i = 0; i < 32; ++i) {
        const int l = l0 + i;
        q[(size_t)l * DD] = s * 0.04f;
        const int th = l + 13, tl = l - 12;
        if (th < LL)  s += p[(size_t)th * DD];
        if (tl >= 0)  s -= p[(size_t)tl * DD];
    }
}

// ---------------------------------------------------------------------------
// LayerNorm over D=512
// ---------------------------------------------------------------------------
__global__ void __launch_bounds__(128)
ln_kernel(const float* __restrict__ in, const float* __restrict__ g,
          const float* __restrict__ bb, float* __restrict__ out)
{
    const int row = blockIdx.x;
    const int tid = threadIdx.x;
    const float4 v = ((const float4*)(in + (size_t)row * DD))[tid];
    float s  = v.x + v.y + v.z + v.w;
    float ss = v.x*v.x + v.y*v.y + v.z*v.z + v.w*v.w;
#pragma unroll
    for (int off = 16; off; off >>= 1) {
        s  += __shfl_xor_sync(0xffffffffu, s , off);
        ss += __shfl_xor_sync(0xffffffffu, ss, off);
    }
    __shared__ float sh[8];
    if ((tid & 31) == 0) { sh[tid >> 5] = s; sh[4 + (tid >> 5)] = ss; }
    __syncthreads();
    s  = sh[0] + sh[1] + sh[2] + sh[3];
    ss = sh[4] + sh[5] + sh[6] + sh[7];
    const float mu  = s * (1.f / DD);
    const float var = ss * (1.f / DD) - mu * mu;
    const float inv = rsqrtf(var + 1e-5f);
    const float4 gg = ((const float4*)g )[tid];
    const float4 bv = ((const float4*)bb)[tid];
    float4 r;
    r.x = (v.x - mu) * inv * gg.x + bv.x;
    r.y = (v.y - mu) * inv * gg.y + bv.y;
    r.z = (v.z - mu) * inv * gg.z + bv.z;
    r.w = (v.w - mu) * inv * gg.w + bv.w;
    ((float4*)(out + (size_t)row * DD))[tid] = r;
}

// ---------------------------------------------------------------------------
extern "C" void kernel_launch(void* const* d_in, const int* in_sizes, int n_in,
                              void* d_out, int out_size)
{
    (void)in_sizes; (void)n_in; (void)out_size;
    const float* x     = (const float*)d_in[0];
    const float* enc   = (const float*)d_in[1];
    const float* saWq  = (const float*)d_in[2];
    const float* sabq  = (const float*)d_in[3];
    const float* saWk  = (const float*)d_in[4];
    const float* sabk  = (const float*)d_in[5];
    const float* saWv  = (const float*)d_in[6];
    const float* sabv  = (const float*)d_in[7];
    const float* saWo  = (const float*)d_in[8];
    const float* sabo  = (const float*)d_in[9];
    const float* caWq  = (const float*)d_in[10];
    const float* cabq  = (const float*)d_in[11];
    const float* caWk  = (const float*)d_in[12];
    const float* cabk  = (const float*)d_in[13];
    const float* caWv  = (const float*)d_in[14];
    const float* cabv  = (const float*)d_in[15];
    const float* caWo  = (const float*)d_in[16];
    const float* cabo  = (const float*)d_in[17];
    const float* ffW1  = (const float*)d_in[18];
    const float* ffb1  = (const float*)d_in[19];
    const float* ffW2  = (const float*)d_in[20];
    const float* ffb2  = (const float*)d_in[21];
    const float* n1g   = (const float*)d_in[22];
    const float* n1b   = (const float*)d_in[23];
    const float* n2g   = (const float*)d_in[24];
    const float* n2b   = (const float*)d_in[25];
    const float* n3g   = (const float*)d_in[26];
    const float* n3b   = (const float*)d_in[27];
    float* out = (float*)d_out;

    float *q, *k, *v, *at, *t, *mm, *xx, *ff;
    cudaGetSymbolAddress((void**)&q , g_q);
    cudaGetSymbolAddress((void**)&k , g_k);
    cudaGetSymbolAddress((void**)&v , g_v);
    cudaGetSymbolAddress((void**)&at, g_at);
    cudaGetSymbolAddress((void**)&t , g_t);
    cudaGetSymbolAddress((void**)&mm, g_m);
    cudaGetSymbolAddress((void**)&xx, g_x);
    cudaGetSymbolAddress((void**)&ff, g_ff);

    const dim3 blk(256);
    const dim3 gP (DD  / 128, MM / 128);     // (4, 64)
    const dim3 gF1(DFF / 128, MM / 128);     // (16, 64)
    const dim3 gAttn(LL / 64, BB * HH);      // (16, 64)
    const dim3 gMov(LL / 32, BB);            // (32, 8)

    // ---- self attention ----
    gemm_mma<false,false><<<gP, blk>>>(x, saWq, sabq, nullptr, q, DD, DD);
    gemm_mma<false,false><<<gP, blk>>>(x, saWk, sabk, nullptr, k, DD, DD);
    gemm_mma<false,false><<<gP, blk>>>(x, saWv, sabv, nullptr, v, DD, DD);
    attn_kernel<<<gAttn, blk>>>(q, k, v, at);
    gemm_mma<true ,false><<<gP, blk>>>(at, saWo, sabo, x, t, DD, DD);
    movavg_kernel<<<gMov, 512>>>(t, mm);
    ln_kernel<<<MM, 128>>>(mm, n1g, n1b, xx);

    // ---- cross attention ----
    gemm_mma<false,false><<<gP, blk>>>(xx , caWq, cabq, nullptr, q, DD, DD);
    gemm_mma<false,false><<<gP, blk>>>(enc, caWk, cabk, nullptr, k, DD, DD);
    gemm_mma<false,false><<<gP, blk>>>(enc, caWv, cabv, nullptr, v, DD, DD);
    attn_kernel<<<gAttn, blk>>>(q, k, v, at);
    gemm_mma<true ,false><<<gP, blk>>>(at, caWo, cabo, xx, t, DD, DD);
    movavg_kernel<<<gMov, 512>>>(t, mm);
    ln_kernel<<<MM, 128>>>(mm, n2g, n2b, xx);

    // ---- feed-forward ----
    gemm_mma<false,true ><<<gF1, blk>>>(xx, ffW1, ffb1, nullptr, ff, DFF, DD);
    gemm_mma<true ,false><<<gP , blk>>>(ff, ffW2, ffb2, xx, t, DD, DFF);
    movavg_kernel<<<gMov, 512>>>(t, mm);
    ln_kernel<<<MM, 128>>>(mm, n3g, n3b, out);
}

// round 10
// speedup vs baseline: 2.4447x; 1.7299x over previous
#include <cuda_runtime.h>
#include <cuda_bf16.h>
#include <math.h>
#include <stdint.h>

// ---------------------------------------------------------------------------
// AutoformerDecoderLayer: B=8, L=1024, D=512, H=8, dk=64, DFF=2048
// Round 10: third submit of the mma.sync tf32 GEMM + attention kernel.
// Audited clean x3; R6==R7 proves content-independent container flakes.
// ---------------------------------------------------------------------------

#define BB 8
#define LL 1024
#define DD 512
#define HH 8
#define DKH 64
#define DFF 2048
#define MM (BB*LL)          // 8192

// --------------------------- scratch (no allocs) ---------------------------
__device__ float g_q  [MM*DD];
__device__ float g_k  [MM*DD];
__device__ float g_v  [MM*DD];
__device__ float g_at [MM*DD];
__device__ float g_t  [MM*DD];
__device__ float g_m  [MM*DD];
__device__ float g_x  [MM*DD];
__device__ float g_ff [MM*DFF];

__device__ __forceinline__ float to_tf32(float x){
    uint32_t y;
    asm("cvt.rna.tf32.f32 %0, %1;" : "=r"(y) : "f"(x));
    return __uint_as_float(y);
}

__device__ __forceinline__ void mma_tf32(float* d, const uint32_t* a, const uint32_t* b){
    asm volatile(
        "mma.sync.aligned.m16n8k8.row.col.f32.tf32.tf32.f32 "
        "{%0,%1,%2,%3}, {%4,%5,%6,%7}, {%8,%9}, {%0,%1,%2,%3};"
        : "+f"(d[0]), "+f"(d[1]), "+f"(d[2]), "+f"(d[3])
        : "r"(a[0]), "r"(a[1]), "r"(a[2]), "r"(a[3]), "r"(b[0]), "r"(b[1]));
}

// ---------------------------------------------------------------------------
// tf32 mma.sync GEMM: C[M,N] = A[M,K] @ W[N,K]^T (+bias, +GELU, +residual)
// CTA 128x128, BK=16 double-buffered, 256 thr (8 warps, warp tile 64x32).
// ---------------------------------------------------------------------------
#define SMS 20                         // padded row stride (floats)

template<bool RES, bool GELU>
__global__ void __launch_bounds__(256, 1)
gemm_mma(const float* __restrict__ A, const float* __restrict__ W,
         const float* __restrict__ bias, const float* __restrict__ R,
         float* __restrict__ C, int Nt, int Kt)
{
    __shared__ float As[2][128][SMS];
    __shared__ float Bs[2][128][SMS];

    const int tid  = threadIdx.x;
    const int lane = tid & 31;
    const int wid  = tid >> 5;
    const int m0 = blockIdx.y * 128;
    const int n0 = blockIdx.x * 128;
    const int wm = (wid & 1) * 64;
    const int wn = (wid >> 1) * 32;
    const int r  = lane >> 2;
    const int cq = lane & 3;

    float acc[4][4][4];
#pragma unroll
    for (int mt = 0; mt < 4; ++mt)
#pragma unroll
        for (int nt = 0; nt < 4; ++nt)
#pragma unroll
            for (int e = 0; e < 4; ++e) acc[mt][nt][e] = 0.f;

    const int fr0 = tid >> 2;
    const int fc4 = (tid & 3) << 2;

#pragma unroll
    for (int i = 0; i < 2; ++i) {
        const int row = fr0 + (i << 6);
        float4 va = *(const float4*)&A[(size_t)(m0 + row) * Kt + fc4];
        va.x = to_tf32(va.x); va.y = to_tf32(va.y);
        va.z = to_tf32(va.z); va.w = to_tf32(va.w);
        *(float4*)&As[0][row][fc4] = va;
        float4 vb = *(const float4*)&W[(size_t)(n0 + row) * Kt + fc4];
        vb.x = to_tf32(vb.x); vb.y = to_tf32(vb.y);
        vb.z = to_tf32(vb.z); vb.w = to_tf32(vb.w);
        *(float4*)&Bs[0][row][fc4] = vb;
    }
    __syncthreads();

    const int S = Kt >> 4;
#pragma unroll 1
    for (int s = 0; s < S; ++s) {
        const int cur = s & 1;

        float4 pa[2], pb[2];
        if (s + 1 < S) {
            const int k0 = (s + 1) << 4;
#pragma unroll
            for (int i = 0; i < 2; ++i) {
                const int row = fr0 + (i << 6);
                pa[i] = *(const float4*)&A[(size_t)(m0 + row) * Kt + k0 + fc4];
                pb[i] = *(const float4*)&W[(size_t)(n0 + row) * Kt + k0 + fc4];
            }
        }

#pragma unroll
        for (int ks = 0; ks < 2; ++ks) {
            const int kc = ks << 3;
            uint32_t af[4][4], bf[4][2];
#pragma unroll
            for (int mt = 0; mt < 4; ++mt) {
                const int mr = wm + mt * 16 + r;
                af[mt][0] = __float_as_uint(As[cur][mr    ][kc + cq    ]);
                af[mt][1] = __float_as_uint(As[cur][mr + 8][kc + cq    ]);
                af[mt][2] = __float_as_uint(As[cur][mr    ][kc + cq + 4]);
                af[mt][3] = __float_as_uint(As[cur][mr + 8][kc + cq + 4]);
            }
#pragma unroll
            for (int nt = 0; nt < 4; ++nt) {
                const int nr = wn + nt * 8 + r;
                bf[nt][0] = __float_as_uint(Bs[cur][nr][kc + cq    ]);
                bf[nt][1] = __float_as_uint(Bs[cur][nr][kc + cq + 4]);
            }
#pragma unroll
            for (int mt = 0; mt < 4; ++mt)
#pragma unroll
                for (int nt = 0; nt < 4; ++nt)
                    mma_tf32(acc[mt][nt], af[mt], bf[nt]);
        }

        if (s + 1 < S) {
            const int nxt = cur ^ 1;
#pragma unroll
            for (int i = 0; i < 2; ++i) {
                const int row = fr0 + (i << 6);
                float4 va = pa[i];
                va.x = to_tf32(va.x); va.y = to_tf32(va.y);
                va.z = to_tf32(va.z); va.w = to_tf32(va.w);
                *(float4*)&As[nxt][row][fc4] = va;
                float4 vb = pb[i];
                vb.x = to_tf32(vb.x); vb.y = to_tf32(vb.y);
                vb.z = to_tf32(vb.z); vb.w = to_tf32(vb.w);
                *(float4*)&Bs[nxt][row][fc4] = vb;
            }
            __syncthreads();
        }
    }

#pragma unroll
    for (int mt = 0; mt < 4; ++mt) {
#pragma unroll
        for (int half = 0; half < 2; ++half) {
            const int row = m0 + wm + mt * 16 + r + half * 8;
#pragma unroll
            for (int nt = 0; nt < 4; ++nt) {
                const int col = n0 + wn + nt * 8 + 2 * cq;
                float v0 = acc[mt][nt][half * 2 + 0];
                float v1 = acc[mt][nt][half * 2 + 1];
                float2 bv = *(const float2*)&bias[col];
                v0 += bv.x; v1 += bv.y;
                if (GELU) {
                    v0 = 0.5f * v0 * (1.f + erff(v0 * 0.70710678118654752f));
                    v1 = 0.5f * v1 * (1.f + erff(v1 * 0.70710678118654752f));
                }
                if (RES) {
                    float2 rv = *(const float2*)&R[(size_t)row * Nt + col];
                    v0 += rv.x; v1 += rv.y;
                }
                *(float2*)&C[(size_t)row * Nt + col] = make_float2(v0, v1);
            }
        }
    }
}

// ---------------------------------------------------------------------------
// mma.sync tf32 flash attention: 64 q x 64 k tiles, dk=64.
// 128 thr / 4 warps; warp w owns q rows {w*16..w*16+7, +8..+15}. Q kept as
// register A-fragments. KP holds K then P; Vs holds V. 35840 B static smem.
// ---------------------------------------------------------------------------
#define KPS 68
#define VSS 72

__global__ void __launch_bounds__(128)
attn_kernel(const float* __restrict__ Q, const float* __restrict__ K,
            const float* __restrict__ V, float* __restrict__ O)
{
    __shared__ float KP[64 * KPS];
    __shared__ float Vs[64 * VSS];

    const int tid  = threadIdx.x;
    const int lane = tid & 31;
    const int w    = tid >> 5;           // 0..3
    const int r    = lane >> 2;          // 0..7
    const int cq   = lane & 3;           // 0..3
    const int b  = blockIdx.y >> 3;
    const int h  = blockIdx.y & 7;
    const int l0q = blockIdx.x << 6;
    const size_t hb = ((size_t)b * LL) * DD + h * DKH;

    // ---- stage Q tile into KP, extract register A-fragments ----
#pragma unroll
    for (int i = 0; i < 8; ++i) {
        const int f   = tid + (i << 7);
        const int row = f >> 4;
        const int c4  = (f & 15) << 2;
        float4 v = *(const float4*)&Q[hb + (size_t)(l0q + row) * DD + c4];
        v.x = to_tf32(v.x); v.y = to_tf32(v.y);
        v.z = to_tf32(v.z); v.w = to_tf32(v.w);
        *(float4*)&KP[row * KPS + c4] = v;
    }
    __syncthreads();

    const int qr = w * 16 + r;
    uint32_t qa[8][4];
#pragma unroll
    for (int kc = 0; kc < 8; ++kc) {
        qa[kc][0] = __float_as_uint(KP[ qr      * KPS + 8 * kc + cq    ]);
        qa[kc][1] = __float_as_uint(KP[(qr + 8) * KPS + 8 * kc + cq    ]);
        qa[kc][2] = __float_as_uint(KP[ qr      * KPS + 8 * kc + cq + 4]);
        qa[kc][3] = __float_as_uint(KP[(qr + 8) * KPS + 8 * kc + cq + 4]);
    }

    float o[8][4];
#pragma unroll
    for (int nt = 0; nt < 8; ++nt)
#pragma unroll
        for (int e = 0; e < 4; ++e) o[nt][e] = 0.f;
    float m0 = -1e30f, m1 = -1e30f, l0 = 0.f, l1 = 0.f;
    const float qpos0 = (float)(l0q + qr);
    const float qpos1 = (float)(l0q + qr + 8);

#pragma unroll 1
    for (int kt = 0; kt < 16; ++kt) {
        const int kbase = kt << 6;
        __syncthreads();                      // prior PV reads done
        // ---- load K -> KP, V -> Vs (RNA tf32) ----
#pragma unroll
        for (int i = 0; i < 8; ++i) {
            const int f   = tid + (i << 7);
            const int row = f >> 4;
            const int c4  = (f & 15) << 2;
            float4 kv = *(const float4*)&K[hb + (size_t)(kbase + row) * DD + c4];
            kv.x = to_tf32(kv.x); kv.y = to_tf32(kv.y);
            kv.z = to_tf32(kv.z); kv.w = to_tf32(kv.w);
            *(float4*)&KP[row * KPS + c4] = kv;
            float4 vv = *(const float4*)&V[hb + (size_t)(kbase + row) * DD + c4];
            vv.x = to_tf32(vv.x); vv.y = to_tf32(vv.y);
            vv.z = to_tf32(vv.z); vv.w = to_tf32(vv.w);
            *(float4*)&Vs[row * VSS + c4] = vv;
        }
        __syncthreads();

        // ---- S = Q K^T ----
        float s[8][4];
#pragma unroll
        for (int nt = 0; nt < 8; ++nt)
#pragma unroll
            for (int e = 0; e < 4; ++e) s[nt][e] = 0.f;
#pragma unroll
        for (int kc = 0; kc < 8; ++kc) {
            uint32_t bf[8][2];
#pragma unroll
            for (int nt = 0; nt < 8; ++nt) {
                const int nr = nt * 8 + r;
                bf[nt][0] = __float_as_uint(KP[nr * KPS + 8 * kc + cq    ]);
                bf[nt][1] = __float_as_uint(KP[nr * KPS + 8 * kc + cq + 4]);
            }
#pragma unroll
            for (int nt = 0; nt < 8; ++nt)
                mma_tf32(s[nt], qa[kc], bf[nt]);
        }

        // ---- online softmax (rows qr, qr+8; quad-local reduction) ----
        float rm0 = -1e30f, rm1 = -1e30f;
#pragma unroll
        for (int nt = 0; nt < 8; ++nt) {
            const float col0 = (float)(kbase + nt * 8 + 2 * cq);
            const float col1 = col0 + 1.f;
            s[nt][0] = s[nt][0] * 0.125f - 0.1f * fabsf(qpos0 - col0);
            s[nt][1] = s[nt][1] * 0.125f - 0.1f * fabsf(qpos0 - col1);
            s[nt][2] = s[nt][2] * 0.125f - 0.1f * fabsf(qpos1 - col0);
            s[nt][3] = s[nt][3] * 0.125f - 0.1f * fabsf(qpos1 - col1);
            rm0 = fmaxf(rm0, fmaxf(s[nt][0], s[nt][1]));
            rm1 = fmaxf(rm1, fmaxf(s[nt][2], s[nt][3]));
        }
        rm0 = fmaxf(rm0, __shfl_xor_sync(0xffffffffu, rm0, 1));
        rm0 = fmaxf(rm0, __shfl_xor_sync(0xffffffffu, rm0, 2));
        rm1 = fmaxf(rm1, __shfl_xor_sync(0xffffffffu, rm1, 1));
        rm1 = fmaxf(rm1, __shfl_xor_sync(0xffffffffu, rm1, 2));
        const float mn0 = fmaxf(m0, rm0);
        const float mn1 = fmaxf(m1, rm1);
        const float a0 = __expf(m0 - mn0);
        const float a1 = __expf(m1 - mn1);
        m0 = mn0; m1 = mn1;
        float rs0 = 0.f, rs1 = 0.f;
#pragma unroll
        for (int nt = 0; nt < 8; ++nt) {
            s[nt][0] = __expf(s[nt][0] - mn0);
            s[nt][1] = __expf(s[nt][1] - mn0);
            s[nt][2] = __expf(s[nt][2] - mn1);
            s[nt][3] = __expf(s[nt][3] - mn1);
            rs0 += s[nt][0] + s[nt][1];
            rs1 += s[nt][2] + s[nt][3];
        }
        rs0 += __shfl_xor_sync(0xffffffffu, rs0, 1);
        rs0 += __shfl_xor_sync(0xffffffffu, rs0, 2);
        rs1 += __shfl_xor_sync(0xffffffffu, rs1, 1);
        rs1 += __shfl_xor_sync(0xffffffffu, rs1, 2);
        l0 = l0 * a0 + rs0;
        l1 = l1 * a1 + rs1;
#pragma unroll
        for (int nt = 0; nt < 8; ++nt) {
            o[nt][0] *= a0; o[nt][1] *= a0;
            o[nt][2] *= a1; o[nt][3] *= a1;
        }

        __syncthreads();                      // all warps done reading K
        // ---- store P into KP (tf32-rounded) ----
#pragma unroll
        for (int nt = 0; nt < 8; ++nt) {
            const int cc = nt * 8 + 2 * cq;
            *(float2*)&KP[ qr      * KPS + cc] =
                make_float2(to_tf32(s[nt][0]), to_tf32(s[nt][1]));
            *(float2*)&KP[(qr + 8) * KPS + cc] =
                make_float2(to_tf32(s[nt][2]), to_tf32(s[nt][3]));
        }
        __syncthreads();

        // ---- O += P V ----
#pragma unroll
        for (int kc = 0; kc < 8; ++kc) {
            uint32_t pa[4];
            pa[0] = __float_as_uint(KP[ qr      * KPS + 8 * kc + cq    ]);
            pa[1] = __float_as_uint(KP[(qr + 8) * KPS + 8 * kc + cq    ]);
            pa[2] = __float_as_uint(KP[ qr      * KPS + 8 * kc + cq + 4]);
            pa[3] = __float_as_uint(KP[(qr + 8) * KPS + 8 * kc + cq + 4]);
            uint32_t vb[8][2];
#pragma unroll
            for (int nt = 0; nt < 8; ++nt) {
                const int nr = nt * 8 + r;
                vb[nt][0] = __float_as_uint(Vs[(8 * kc + cq    ) * VSS + nr]);
                vb[nt][1] = __float_as_uint(Vs[(8 * kc + cq + 4) * VSS + nr]);
            }
#pragma unroll
            for (int nt = 0; nt < 8; ++nt)
                mma_tf32(o[nt], pa, vb[nt]);
        }
    }

    // ---- epilogue ----
    const float inv0 = 1.f / l0;
    const float inv1 = 1.f / l1;
#pragma unroll
    for (int nt = 0; nt < 8; ++nt) {
        const int cc = nt * 8 + 2 * cq;
        *(float2*)&O[hb + (size_t)(l0q + qr    ) * DD + cc] =
            make_float2(o[nt][0] * inv0, o[nt][1] * inv0);
        *(float2*)&O[hb + (size_t)(l0q + qr + 8) * DD + cc] =
            make_float2(o[nt][2] * inv1, o[nt][3] * inv1);
    }
}

// ---------------------------------------------------------------------------
// Moving average (k=25, stride 1, pad 12, count_include_pad)
// ---------------------------------------------------------------------------
__global__ void movavg_kernel(const float* __restrict__ in, float* __restrict__ out)
{
    const int d  = threadIdx.x;
    const int b  = blockIdx.y;
    const int l0 = blockIdx.x * 32;
    const float* p = in  + ((size_t)b * LL) * DD + d;
    float*       q = out + ((size_t)b * LL) * DD + d;

    float s = 0.f;
#pragma unroll 1
    for (int t = l0 - 12; t <= l0 + 12; ++t)
        if (t >= 0 && t < LL) s += p[(size_t)t * DD];
#pragma unroll 1
    for (int i = 0; i < 32; ++i) {
        const int l = l0 + i;
        q[(size_t)l * DD] = s * 0.04f;
        const int th = l + 13, tl = l - 12;
        if (th < LL)  s += p[(size_t)th * DD];
        if (tl >= 0)  s -= p[(size_t)tl * DD];
    }
}

// ---------------------------------------------------------------------------
// LayerNorm over D=512
// ---------------------------------------------------------------------------
__global__ void __launch_bounds__(128)
ln_kernel(const float* __restrict__ in, const float* __restrict__ g,
          const float* __restrict__ bb, float* __restrict__ out)
{
    const int row = blockIdx.x;
    const int tid = threadIdx.x;
    const float4 v = ((const float4*)(in + (size_t)row * DD))[tid];
    float s  = v.x + v.y + v.z + v.w;
    float ss = v.x*v.x + v.y*v.y + v.z*v.z + v.w*v.w;
#pragma unroll
    for (int off = 16; off; off >>= 1) {
        s  += __shfl_xor_sync(0xffffffffu, s , off);
        ss += __shfl_xor_sync(0xffffffffu, ss, off);
    }
    __shared__ float sh[8];
    if ((tid & 31) == 0) { sh[tid >> 5] = s; sh[4 + (tid >> 5)] = ss; }
    __syncthreads();
    s  = sh[0] + sh[1] + sh[2] + sh[3];
    ss = sh[4] + sh[5] + sh[6] + sh[7];
    const float mu  = s * (1.f / DD);
    const float var = ss * (1.f / DD) - mu * mu;
    const float inv = rsqrtf(var + 1e-5f);
    const float4 gg = ((const float4*)g )[tid];
    const float4 bv = ((const float4*)bb)[tid];
    float4 r;
    r.x = (v.x - mu) * inv * gg.x + bv.x;
    r.y = (v.y - mu) * inv * gg.y + bv.y;
    r.z = (v.z - mu) * inv * gg.z + bv.z;
    r.w = (v.w - mu) * inv * gg.w + bv.w;
    ((float4*)(out + (size_t)row * DD))[tid] = r;
}

// ---------------------------------------------------------------------------
extern "C" void kernel_launch(void* const* d_in, const int* in_sizes, int n_in,
                              void* d_out, int out_size)
{
    (void)in_sizes; (void)n_in; (void)out_size;
    const float* x     = (const float*)d_in[0];
    const float* enc   = (const float*)d_in[1];
    const float* saWq  = (const float*)d_in[2];
    const float* sabq  = (const float*)d_in[3];
    const float* saWk  = (const float*)d_in[4];
    const float* sabk  = (const float*)d_in[5];
    const float* saWv  = (const float*)d_in[6];
    const float* sabv  = (const float*)d_in[7];
    const float* saWo  = (const float*)d_in[8];
    const float* sabo  = (const float*)d_in[9];
    const float* caWq  = (const float*)d_in[10];
    const float* cabq  = (const float*)d_in[11];
    const float* caWk  = (const float*)d_in[12];
    const float* cabk  = (const float*)d_in[13];
    const float* caWv  = (const float*)d_in[14];
    const float* cabv  = (const float*)d_in[15];
    const float* caWo  = (const float*)d_in[16];
    const float* cabo  = (const float*)d_in[17];
    const float* ffW1  = (const float*)d_in[18];
    const float* ffb1  = (const float*)d_in[19];
    const float* ffW2  = (const float*)d_in[20];
    const float* ffb2  = (const float*)d_in[21];
    const float* n1g   = (const float*)d_in[22];
    const float* n1b   = (const float*)d_in[23];
    const float* n2g   = (const float*)d_in[24];
    const float* n2b   = (const float*)d_in[25];
    const float* n3g   = (const float*)d_in[26];
    const float* n3b   = (const float*)d_in[27];
    float* out = (float*)d_out;

    float *q, *k, *v, *at, *t, *mm, *xx, *ff;
    cudaGetSymbolAddress((void**)&q , g_q);
    cudaGetSymbolAddress((void**)&k , g_k);
    cudaGetSymbolAddress((void**)&v , g_v);
    cudaGetSymbolAddress((void**)&at, g_at);
    cudaGetSymbolAddress((void**)&t , g_t);
    cudaGetSymbolAddress((void**)&mm, g_m);
    cudaGetSymbolAddress((void**)&xx, g_x);
    cudaGetSymbolAddress((void**)&ff, g_ff);

    const dim3 blk(256);
    const dim3 gP (DD  / 128, MM / 128);     // (4, 64)
    const dim3 gF1(DFF / 128, MM / 128);     // (16, 64)
    const dim3 gAttn(LL / 64, BB * HH);      // (16, 64), 128 thr
    const dim3 gMov(LL / 32, BB);            // (32, 8)

    // ---- self attention ----
    gemm_mma<false,false><<<gP, blk>>>(x, saWq, sabq, nullptr, q, DD, DD);
    gemm_mma<false,false><<<gP, blk>>>(x, saWk, sabk, nullptr, k, DD, DD);
    gemm_mma<false,false><<<gP, blk>>>(x, saWv, sabv, nullptr, v, DD, DD);
    attn_kernel<<<gAttn, 128>>>(q, k, v, at);
    gemm_mma<true ,false><<<gP, blk>>>(at, saWo, sabo, x, t, DD, DD);
    movavg_kernel<<<gMov, 512>>>(t, mm);
    ln_kernel<<<MM, 128>>>(mm, n1g, n1b, xx);

    // ---- cross attention ----
    gemm_mma<false,false><<<gP, blk>>>(xx , caWq, cabq, nullptr, q, DD, DD);
    gemm_mma<false,false><<<gP, blk>>>(enc, caWk, cabk, nullptr, k, DD, DD);
    gemm_mma<false,false><<<gP, blk>>>(enc, caWv, cabv, nullptr, v, DD, DD);
    attn_kernel<<<gAttn, 128>>>(q, k, v, at);
    gemm_mma<true ,false><<<gP, blk>>>(at, caWo, cabo, xx, t, DD, DD);
    movavg_kernel<<<gMov, 512>>>(t, mm);
    ln_kernel<<<MM, 128>>>(mm, n2g, n2b, xx);

    // ---- feed-forward ----
    gemm_mma<false,true ><<<gF1, blk>>>(xx, ffW1, ffb1, nullptr, ff, DFF, DD);
    gemm_mma<true ,false><<<gP , blk>>>(ff, ffW2, ffb2, xx, t, DD, DFF);
    movavg_kernel<<<gMov, 512>>>(t, mm);
    ln_kernel<<<MM, 128>>>(mm, n3g, n3b, out);
}